// round 16
// baseline (speedup 1.0000x reference)
#include <cuda_runtime.h>
#include <cuda_fp16.h>
#include <mma.h>
#include <cstdint>
#include <cstddef>

using namespace nvcuda;

// ---------------- problem constants ----------------
#define BATCH   32
#define SEQL    576                 // 24*24 tokens
#define MTOK    (BATCH*SEQL)        // 18432
#define DIMV    192
#define DIN     384                 // 2*DIM
#define DSTATE  16
#define DTRANK  12
#define NPROJP  64                  // padded proj row stride (real cols: 44)
#define CH      8                   // scan chunks
#define CHL     (SEQL/CH)           // 72 tokens per chunk

// ---------------- scratch (device globals; no allocation) ----------------
__device__ float  g_tok [(size_t)MTOK * DIMV];            // fp32 (LN in place)
__device__ __half g_xi  [2][(size_t)MTOK * DIN];          // raw x (pre-conv)
__device__ __half g_zs  [2][(size_t)MTOK * DIN];          // silu(z)
__device__ __half g_xc  [2][(size_t)MTOK * DIN];          // silu(conv(x))
__device__ float  g_proj[2][(size_t)MTOK * NPROJP];       // [dt_raw|B|C|pad]
#define NPART (2*BATCH*CH*DIN)
__device__ float4 g_hout[(size_t)NPART*4];
__device__ float4 g_pf  [(size_t)NPART*4];
__device__ float4 g_w   [(size_t)NPART*4];
__device__ float  g_pacc[NPART];
__device__ float  g_ysum[2][BATCH * DIN];

__device__ __forceinline__ float4 h4tof4(uint2 u) {
    float2 a = __half22float2(*(__half2*)&u.x);
    float2 b = __half22float2(*(__half2*)&u.y);
    return make_float4(a.x, a.y, b.x, b.y);
}

// ---------------- shared GEMM geometry --------------------------------------
#define MT 128
#define NT 64
#define KT 32
#define SBK 40
#define ASZ (MT*SBK)
#define BSZ (NT*SBK)
#define GEMM_SMEM 32768

#define CVTSTOREH(dst, off, v) do {                                           \
    __half2 h0_ = __floats2half2_rn((v).x, (v).y);                            \
    __half2 h1_ = __floats2half2_rn((v).z, (v).w);                            \
    *(__half2*)&(dst)[(off)]     = h0_;                                       \
    *(__half2*)&(dst)[(off) + 2] = h1_;                                       \
} while (0)

// ---------------- generic fp16 WMMA GEMM (fp32 A in GMEM) -------------------
// C[M,Nout] = A[M,K] @ W[Nw,K]^T. Block 128x64x32, 8 warps, warp 32x32.
// IMC: implicit im2col of x[32,3,384,384] (16x16 patches) as A.
// ZSPLIT: out cols [0,DIN)->Cx raw half; [DIN,2DIN)->Cz silu'd half (stride DIN);
//         otherwise fp32 store_matrix_sync into Cx.
template<bool IMC, bool ZSPLIT>
__global__ __launch_bounds__(256) void gemm_fp16_kernel(
    const float* __restrict__ A0, const float* __restrict__ A1,
    const float* __restrict__ W0, const float* __restrict__ W1,
    void* __restrict__ Cx0, void* __restrict__ Cx1,
    void* __restrict__ Cz0, void* __restrict__ Cz1,
    int K, int Nw, int Nout)
{
    extern __shared__ __half sm[];
    __half* As = sm;
    __half* Bs = sm + 2*ASZ;

    const float* A = blockIdx.z ? A1 : A0;
    const float* W = blockIdx.z ? W1 : W0;
    void* Cx = blockIdx.z ? Cx1 : Cx0;
    void* Cz = blockIdx.z ? Cz1 : Cz0;

    const int tid  = threadIdx.x;
    const int warp = tid >> 5;
    const int lane = tid & 31;
    const int wm   = warp >> 1;
    const int wn   = warp & 1;
    const int m0 = blockIdx.y * MT;
    const int n0 = blockIdx.x * NT;
    const int ar = tid >> 3, akc = (tid & 7) * 4;

    int rb[4];
    if (IMC) {
        #pragma unroll
        for (int i = 0; i < 4; i++) {
            int tok = m0 + ar + i*32;
            int b = tok / SEQL, rl = tok - b*SEQL;
            int hp = rl / 24, wp = rl - hp*24;
            rb[i] = b*442368 + hp*6144 + wp*16;
        }
    }

    wmma::fragment<wmma::accumulator,16,16,16,float> acc[2][2];
    #pragma unroll
    for (int i = 0; i < 2; i++)
        #pragma unroll
        for (int j = 0; j < 2; j++)
            wmma::fill_fragment(acc[i][j], 0.0f);

    float4 pa[4], pb[2];

    #define LOADT(k0)  do {                                                   \
        if (IMC) {                                                            \
            int k_ = (k0) + akc;                                              \
            int c_ = k_ >> 8, pq_ = k_ & 255;                                 \
            int koff_ = c_*147456 + (pq_ >> 4)*384 + (pq_ & 15);              \
            _Pragma("unroll")                                                 \
            for (int i = 0; i < 4; i++)                                       \
                pa[i] = *(const float4*)&A[rb[i] + koff_];                    \
        } else {                                                              \
            _Pragma("unroll")                                                 \
            for (int i = 0; i < 4; i++)                                       \
                pa[i] = *(const float4*)&A[(size_t)(m0 + ar + i*32)*K + (k0) + akc]; \
        }                                                                     \
        _Pragma("unroll")                                                     \
        for (int i = 0; i < 2; i++) {                                         \
            int r_ = ar + i*32;                                               \
            pb[i] = (n0 + r_ < Nw)                                            \
                ? *(const float4*)&W[(size_t)(n0 + r_)*K + (k0) + akc]        \
                : make_float4(0.f,0.f,0.f,0.f);                               \
        }                                                                     \
    } while (0)

    #define STORET(buf)  do {                                                 \
        _Pragma("unroll")                                                     \
        for (int i = 0; i < 4; i++)                                           \
            CVTSTOREH(As, (buf)*ASZ + (ar + i*32)*SBK + akc, pa[i]);          \
        _Pragma("unroll")                                                     \
        for (int i = 0; i < 2; i++)                                           \
            CVTSTOREH(Bs, (buf)*BSZ + (ar + i*32)*SBK + akc, pb[i]);          \
    } while (0)

    LOADT(0);
    STORET(0);
    __syncthreads();

    int buf = 0;
    for (int k0 = 0; k0 < K; k0 += KT) {
        const bool more = (k0 + KT) < K;
        if (more) LOADT(k0 + KT);
        #pragma unroll
        for (int kk = 0; kk < KT; kk += 16) {
            wmma::fragment<wmma::matrix_b,16,16,16,__half,wmma::col_major> bf[2];
            #pragma unroll
            for (int j = 0; j < 2; j++)
                wmma::load_matrix_sync(bf[j], &Bs[buf*BSZ + (wn*32 + j*16)*SBK + kk], SBK);
            #pragma unroll
            for (int i = 0; i < 2; i++) {
                wmma::fragment<wmma::matrix_a,16,16,16,__half,wmma::row_major> af;
                wmma::load_matrix_sync(af, &As[buf*ASZ + (wm*32 + i*16)*SBK + kk], SBK);
                #pragma unroll
                for (int j = 0; j < 2; j++)
                    wmma::mma_sync(acc[i][j], af, bf[j], acc[i][j]);
            }
        }
        if (more) STORET(buf ^ 1);
        __syncthreads();
        buf ^= 1;
    }
    #undef LOADT
    #undef STORET

    if (ZSPLIT) {
        __syncthreads();
        float* stage = reinterpret_cast<float*>(sm) + warp * 1024;
        #pragma unroll
        for (int i = 0; i < 2; i++)
            #pragma unroll
            for (int j = 0; j < 2; j++)
                wmma::store_matrix_sync(&stage[i*16*32 + j*16], acc[i][j], 32,
                                        wmma::mem_row_major);
        __syncwarp();
        int nbase = n0 + wn*32;
        bool isz = nbase >= DIN;
        __half* Cd = reinterpret_cast<__half*>(isz ? Cz : Cx);
        int nc0 = (isz ? nbase - DIN : nbase) + (lane & 3) * 8;
        #pragma unroll
        for (int r4 = 0; r4 < 4; r4++) {
            int row = r4*8 + (lane >> 2);
            const float* src = &stage[row*32 + (lane & 3)*8];
            __half2 h[4];
            #pragma unroll
            for (int c = 0; c < 4; c++) {
                float v0 = src[c*2], v1 = src[c*2 + 1];
                if (isz) {
                    v0 = v0 * __frcp_rn(1.0f + __expf(-v0));
                    v1 = v1 * __frcp_rn(1.0f + __expf(-v1));
                }
                h[c] = __floats2half2_rn(v0, v1);
            }
            *(uint4*)&Cd[(size_t)(m0 + wm*32 + row)*Nout + nc0] = *(uint4*)h;
        }
    } else {
        float* C = (float*)Cx;
        #pragma unroll
        for (int i = 0; i < 2; i++)
            #pragma unroll
            for (int j = 0; j < 2; j++)
                wmma::store_matrix_sync(
                    &C[(size_t)(m0 + wm*32 + i*16)*Nout + n0 + wn*32 + j*16],
                    acc[i][j], Nout, wmma::mem_row_major);
    }
}

// ---------------- dedicated x-proj GEMM with fused conv+silu ----------------
// proj[M,NPROJP] = conv_silu(xi)[M,DIN] @ Wx[44,DIN]^T  (pad cols zero)
// The A-loader computes the depthwise causal (dir 0) / anticausal (dir 1)
// conv + silu in fp32 from half xi, feeds half into smem, AND stores to g_xc.
// grid = (1, MTOK/MT, 2). Each (token,channel) produced exactly once.
__global__ __launch_bounds__(256) void xproj_conv_kernel(
    const __half* __restrict__ xi0, const __half* __restrict__ xi1,
    const float* __restrict__ W0,  const float* __restrict__ W1,
    float* __restrict__ C0,        float* __restrict__ C1,
    __half* __restrict__ xc0,      __half* __restrict__ xc1,
    const float* __restrict__ CW0, const float* __restrict__ CW1,
    const float* __restrict__ CB0, const float* __restrict__ CB1)
{
    extern __shared__ __half sm[];
    __half* As = sm;
    __half* Bs = sm + 2*ASZ;

    const __half* Ah = blockIdx.z ? xi1 : xi0;
    const float*  W  = blockIdx.z ? W1  : W0;
    float*        C  = blockIdx.z ? C1  : C0;
    __half*       XC = blockIdx.z ? xc1 : xc0;
    const float*  CW = blockIdx.z ? CW1 : CW0;
    const float*  CB = blockIdx.z ? CB1 : CB0;
    const int     cs = blockIdx.z ? -1 : 1;

    const int tid  = threadIdx.x;
    const int warp = tid >> 5;
    const int wm   = warp >> 1;
    const int wn   = warp & 1;
    const int m0 = blockIdx.y * MT;
    const int ar = tid >> 3, akc = (tid & 7) * 4;

    int bi[4], li[4];
    #pragma unroll
    for (int i = 0; i < 4; i++) {
        int tok = m0 + ar + i*32;
        bi[i] = tok / SEQL;
        li[i] = tok - bi[i]*SEQL;
    }

    wmma::fragment<wmma::accumulator,16,16,16,float> acc[2][2];
    #pragma unroll
    for (int i = 0; i < 2; i++)
        #pragma unroll
        for (int j = 0; j < 2; j++)
            wmma::fill_fragment(acc[i][j], 0.0f);

    uint2  pah[4];
    float4 pb[2];

    auto load_tiles = [&](int k0) {
        int kc = k0 + akc;
        // conv weights transposed to per-tap vectors
        float4 wr0 = *(const float4*)&CW[(kc+0)*4];
        float4 wr1 = *(const float4*)&CW[(kc+1)*4];
        float4 wr2 = *(const float4*)&CW[(kc+2)*4];
        float4 wr3 = *(const float4*)&CW[(kc+3)*4];
        float4 t0 = make_float4(wr0.x, wr1.x, wr2.x, wr3.x);
        float4 t1 = make_float4(wr0.y, wr1.y, wr2.y, wr3.y);
        float4 t2 = make_float4(wr0.z, wr1.z, wr2.z, wr3.z);
        float4 t3 = make_float4(wr0.w, wr1.w, wr2.w, wr3.w);
        float4 cbias = *(const float4*)&CB[kc];
        #pragma unroll
        for (int i = 0; i < 4; i++) {
            float4 r = cbias;
            size_t rowb = (size_t)bi[i]*SEQL*DIN + kc;
            #pragma unroll
            for (int j = 0; j < 4; j++) {
                int off = li[i] - (3-j)*cs;
                if ((unsigned)off < SEQL) {
                    float4 v = h4tof4(*(const uint2*)&Ah[rowb + (size_t)off*DIN]);
                    float4 t = (j==0)?t0:(j==1)?t1:(j==2)?t2:t3;
                    r.x = fmaf(t.x, v.x, r.x);
                    r.y = fmaf(t.y, v.y, r.y);
                    r.z = fmaf(t.z, v.z, r.z);
                    r.w = fmaf(t.w, v.w, r.w);
                }
            }
            r.x = r.x * __frcp_rn(1.0f + __expf(-r.x));
            r.y = r.y * __frcp_rn(1.0f + __expf(-r.y));
            r.z = r.z * __frcp_rn(1.0f + __expf(-r.z));
            r.w = r.w * __frcp_rn(1.0f + __expf(-r.w));
            *(__half2*)&pah[i].x = __floats2half2_rn(r.x, r.y);
            *(__half2*)&pah[i].y = __floats2half2_rn(r.z, r.w);
            *(uint2*)&XC[rowb + (size_t)li[i]*DIN] = pah[i];
        }
        #pragma unroll
        for (int i = 0; i < 2; i++) {
            int rr = ar + i*32;
            pb[i] = (rr < 44)
                ? *(const float4*)&W[(size_t)rr*DIN + k0 + akc]
                : make_float4(0.f,0.f,0.f,0.f);
        }
    };
    auto store_tiles = [&](int buf) {
        #pragma unroll
        for (int i = 0; i < 4; i++)
            *(uint2*)&As[buf*ASZ + (ar + i*32)*SBK + akc] = pah[i];
        #pragma unroll
        for (int i = 0; i < 2; i++)
            CVTSTOREH(Bs, buf*BSZ + (ar + i*32)*SBK + akc, pb[i]);
    };

    load_tiles(0);
    store_tiles(0);
    __syncthreads();

    int buf = 0;
    for (int k0 = 0; k0 < DIN; k0 += KT) {
        const bool more = (k0 + KT) < DIN;
        if (more) load_tiles(k0 + KT);
        #pragma unroll
        for (int kk = 0; kk < KT; kk += 16) {
            wmma::fragment<wmma::matrix_b,16,16,16,__half,wmma::col_major> bf[2];
            #pragma unroll
            for (int j = 0; j < 2; j++)
                wmma::load_matrix_sync(bf[j], &Bs[buf*BSZ + (wn*32 + j*16)*SBK + kk], SBK);
            #pragma unroll
            for (int i = 0; i < 2; i++) {
                wmma::fragment<wmma::matrix_a,16,16,16,__half,wmma::row_major> af;
                wmma::load_matrix_sync(af, &As[buf*ASZ + (wm*32 + i*16)*SBK + kk], SBK);
                #pragma unroll
                for (int j = 0; j < 2; j++)
                    wmma::mma_sync(acc[i][j], af, bf[j], acc[i][j]);
            }
        }
        if (more) store_tiles(buf ^ 1);
        __syncthreads();
        buf ^= 1;
    }

    #pragma unroll
    for (int i = 0; i < 2; i++)
        #pragma unroll
        for (int j = 0; j < 2; j++)
            wmma::store_matrix_sync(
                &C[(size_t)(m0 + wm*32 + i*16)*NPROJP + wn*32 + j*16],
                acc[i][j], NPROJP, wmma::mem_row_major);
}

// ---------------- LayerNorm over DIM=192 (patch bias folded in) -------------
__global__ void ln_kernel(float* __restrict__ tok, const float* __restrict__ pb,
                          const float* __restrict__ g, const float* __restrict__ b) {
    int row  = blockIdx.x * 8 + (threadIdx.x >> 5);
    int lane = threadIdx.x & 31;
    float* p = tok + (size_t)row * DIMV;
    float v[6]; float s = 0.f;
    #pragma unroll
    for (int i = 0; i < 6; i++) {
        int c = lane + i*32;
        v[i] = p[c] + pb[c];
        s += v[i];
    }
    #pragma unroll
    for (int o = 16; o; o >>= 1) s += __shfl_xor_sync(0xffffffffu, s, o);
    float mu = s * (1.0f/192.0f);
    float q = 0.f;
    #pragma unroll
    for (int i = 0; i < 6; i++) { float d = v[i] - mu; q = fmaf(d, d, q); }
    #pragma unroll
    for (int o = 16; o; o >>= 1) q += __shfl_xor_sync(0xffffffffu, q, o);
    float rstd = rsqrtf(q * (1.0f/192.0f) + 1e-5f);
    #pragma unroll
    for (int i = 0; i < 6; i++) {
        int c = lane + i*32;
        p[c] = (v[i] - mu) * rstd * g[c] + b[c];
    }
}

// ---------------- scan part: one THREAD per (dir,b,chunk,d) ------------------
__global__ __launch_bounds__(128) void scan_part_kernel(
    const float* __restrict__ Alf, const float* __restrict__ Df,
    const float* __restrict__ Alb, const float* __restrict__ Db,
    const float* __restrict__ dtwf, const float* __restrict__ dtbf,
    const float* __restrict__ dtwb, const float* __restrict__ dtbb)
{
    __shared__ float sproj[CHL][48];
    const int tid  = threadIdx.x;
    const int c    = blockIdx.y;
    const int zz   = blockIdx.z;
    const int dir  = zz / BATCH;
    const int b    = zz - dir*BATCH;
    const int d    = blockIdx.x * 128 + tid;
    const int step = dir ? -1 : 1;
    const int r0   = b*SEQL + (dir ? (SEQL - 1 - c*CHL) : c*CHL);

    const float* pp = g_proj[dir];
    for (int idx = tid; idx < CHL*12; idx += 128) {
        int row = idx / 12, q = idx - row*12;
        int rr = r0 + step*row;
        *(float4*)&sproj[row][q*4] = *(const float4*)&pp[(size_t)rr*NPROJP + q*4];
    }

    const float* Alog = dir ? Alb : Alf;
    float Dv = (dir ? Db : Df)[d];
    float a[16];
    #pragma unroll
    for (int j = 0; j < 16; j++) a[j] = -__expf(Alog[d*DSTATE + j]);
    const float* dtwp = dir ? dtwb : dtwf;
    float dtbias = (dir ? dtbb : dtbf)[d];
    float dtw[12];
    #pragma unroll
    for (int k = 0; k < 12; k++) dtw[k] = dtwp[d*DTRANK + k];
    const __half* xcp = g_xc[dir];
    const __half* zp  = g_zs[dir];

    float h[16], p[16], w[16];
    #pragma unroll
    for (int j = 0; j < 16; j++) { h[j] = 0.f; p[j] = 1.f; w[j] = 0.f; }
    float acc = 0.f;
    __syncthreads();

    int r = r0;
    for (int t = 0; t < CHL; t++, r += step) {
        size_t rd = (size_t)r * DIN + d;
        float xcv = __half2float(xcp[rd]);
        float zsv = __half2float(zp[rd]);
        const float* row = sproj[t];
        float dp = dtbias;
        #pragma unroll
        for (int k = 0; k < 12; k++) dp = fmaf(row[k], dtw[k], dp);
        float dtv = fmaxf(dp, 0.0f) + __logf(1.0f + __expf(-fabsf(dp)));
        float dtx = dtv * xcv;
        float part = 0.f;
        #pragma unroll
        for (int j = 0; j < 16; j++) {
            float Bj = row[DTRANK + j];
            float Cj = row[DTRANK + DSTATE + j];
            float e  = __expf(dtv * a[j]);
            h[j] = fmaf(e, h[j], dtx * Bj);
            p[j] *= e;
            w[j] = fmaf(zsv * Cj, p[j], w[j]);
            part = fmaf(h[j], Cj, part);
        }
        acc = fmaf(fmaf(xcv, Dv, part), zsv, acc);
    }

    size_t part_i = ((size_t)(zz*CH + c)*DIN + d);
    #pragma unroll
    for (int q = 0; q < 4; q++) {
        g_hout[part_i*4 + q] = make_float4(h[q*4], h[q*4+1], h[q*4+2], h[q*4+3]);
        g_pf  [part_i*4 + q] = make_float4(p[q*4], p[q*4+1], p[q*4+2], p[q*4+3]);
        g_w   [part_i*4 + q] = make_float4(w[q*4], w[q*4+1], w[q*4+2], w[q*4+3]);
    }
    g_pacc[part_i] = acc;
}

// ---------------- scan combine: one thread per (dir,b,d) --------------------
__global__ __launch_bounds__(128) void scan_combine_kernel() {
    int gid = blockIdx.x * 128 + threadIdx.x;
    if (gid >= 2 * BATCH * DIN) return;
    int zz = gid / DIN;
    int d  = gid - zz * DIN;
    float hin[16];
    #pragma unroll
    for (int j = 0; j < 16; j++) hin[j] = 0.f;
    float acc = 0.f;
    #pragma unroll
    for (int c = 0; c < CH; c++) {
        size_t part_i = ((size_t)(zz*CH + c)*DIN + d);
        float dv = 0.f;
        #pragma unroll
        for (int q = 0; q < 4; q++) {
            float4 wv = g_w[part_i*4 + q];
            dv = fmaf(wv.x, hin[q*4+0], dv);
            dv = fmaf(wv.y, hin[q*4+1], dv);
            dv = fmaf(wv.z, hin[q*4+2], dv);
            dv = fmaf(wv.w, hin[q*4+3], dv);
        }
        acc += g_pacc[part_i] + dv;
        #pragma unroll
        for (int q = 0; q < 4; q++) {
            float4 ho = g_hout[part_i*4 + q];
            float4 pf = g_pf[part_i*4 + q];
            hin[q*4+0] = fmaf(pf.x, hin[q*4+0], ho.x);
            hin[q*4+1] = fmaf(pf.y, hin[q*4+1], ho.y);
            hin[q*4+2] = fmaf(pf.z, hin[q*4+2], ho.z);
            hin[q*4+3] = fmaf(pf.w, hin[q*4+3], ho.w);
        }
    }
    int dir = zz / BATCH, b = zz - dir*BATCH;
    g_ysum[dir][b*DIN + d] = acc;
}

// ---------------- head: mean -> out_proj (both dirs) -> fc ------------------
__global__ void head_kernel(const float* __restrict__ fow, const float* __restrict__ bow,
                            const float* __restrict__ fcw, const float* __restrict__ fcb,
                            float* __restrict__ out) {
    int b = blockIdx.x;
    __shared__ float ys0[DIN], ys1[DIN], o[DIMV];
    int t = threadIdx.x;
    for (int i = t; i < DIN; i += DIMV) {
        ys0[i] = g_ysum[0][b*DIN + i] * (1.0f/SEQL);
        ys1[i] = g_ysum[1][b*DIN + i] * (1.0f/SEQL);
    }
    __syncthreads();
    float acc = 0.f;
    #pragma unroll 4
    for (int di = 0; di < DIN; di++)
        acc = fmaf(ys0[di], fow[(size_t)t*DIN + di], fmaf(ys1[di], bow[(size_t)t*DIN + di], acc));
    o[t] = acc;
    __syncthreads();
    if (t < 4) {
        float s = fcb[t];
        #pragma unroll 4
        for (int d = 0; d < DIMV; d++) s = fmaf(o[d], fcw[t*DIMV + d], s);
        out[b*4 + t] = s;
    }
}

// ---------------- launch ----------------------------------------------------
extern "C" void kernel_launch(void* const* d_in, const int* in_sizes, int n_in,
                              void* d_out, int out_size) {
    (void)in_sizes; (void)n_in; (void)out_size;
    const float* x       = (const float*)d_in[0];
    const float* patch_w = (const float*)d_in[1];
    const float* patch_b = (const float*)d_in[2];
    const float* ln_g    = (const float*)d_in[3];
    const float* ln_b    = (const float*)d_in[4];
    const float* fc_w    = (const float*)d_in[5];
    const float* fc_b    = (const float*)d_in[6];
    const float* P[2][9];
    for (int dir = 0; dir < 2; dir++)
        for (int i = 0; i < 9; i++)
            P[dir][i] = (const float*)d_in[7 + dir*9 + i];

    float *tok, *proj;
    __half *xi, *zs, *xc;
    cudaGetSymbolAddress((void**)&tok,  g_tok);
    cudaGetSymbolAddress((void**)&xi,   g_xi);
    cudaGetSymbolAddress((void**)&zs,   g_zs);
    cudaGetSymbolAddress((void**)&xc,   g_xc);
    cudaGetSymbolAddress((void**)&proj, g_proj);

    cudaFuncSetAttribute(gemm_fp16_kernel<true,false>,
                         cudaFuncAttributeMaxDynamicSharedMemorySize, GEMM_SMEM);
    cudaFuncSetAttribute(gemm_fp16_kernel<false,true>,
                         cudaFuncAttributeMaxDynamicSharedMemorySize, GEMM_SMEM);
    cudaFuncSetAttribute(xproj_conv_kernel,
                         cudaFuncAttributeMaxDynamicSharedMemorySize, GEMM_SMEM);

    // 1. patch embed GEMM with implicit im2col (bias folded into LN)
    gemm_fp16_kernel<true,false><<<dim3(DIMV/NT, MTOK/MT, 1), 256, GEMM_SMEM>>>(
        x, x, patch_w, patch_w, tok, tok, tok, tok, 768, DIMV, DIMV);
    // 2. layernorm in place (adds patch_b first)
    ln_kernel<<<MTOK/8, 256>>>(tok, patch_b, ln_g, ln_b);
    // 3. in-projection, both dirs; x -> g_xi (half), z -> g_zs (silu, half)
    gemm_fp16_kernel<false,true><<<dim3((2*DIN)/NT, MTOK/MT, 2), 256, GEMM_SMEM>>>(
        tok, tok, P[0][0], P[1][0],
        xi, xi + (size_t)MTOK*DIN,
        zs, zs + (size_t)MTOK*DIN, DIMV, 2*DIN, DIN);
    // 4. x-projection with fused conv+silu; also writes g_xc
    xproj_conv_kernel<<<dim3(1, MTOK/MT, 2), 256, GEMM_SMEM>>>(
        xi, xi + (size_t)MTOK*DIN, P[0][3], P[1][3],
        proj, proj + (size_t)MTOK*NPROJP,
        xc, xc + (size_t)MTOK*DIN,
        P[0][1], P[1][1], P[0][2], P[1][2]);
    // 5. chunked selective scan (dt fused): parts then combine
    scan_part_kernel<<<dim3(DIN/128, CH, 2*BATCH), 128>>>(
        P[0][6], P[0][7], P[1][6], P[1][7],
        P[0][4], P[0][5], P[1][4], P[1][5]);
    scan_combine_kernel<<<(2*BATCH*DIN + 127)/128, 128>>>();
    // 6. head: mean-pool -> out_w (both dirs) -> fc
    head_kernel<<<BATCH, DIMV>>>(P[0][8], P[1][8], fc_w, fc_b, (float*)d_out);
}

// round 17
// speedup vs baseline: 1.1040x; 1.1040x over previous
#include <cuda_runtime.h>
#include <cuda_fp16.h>
#include <mma.h>
#include <cstdint>
#include <cstddef>

using namespace nvcuda;

// ---------------- problem constants ----------------
#define BATCH   32
#define SEQL    576                 // 24*24 tokens
#define MTOK    (BATCH*SEQL)        // 18432
#define DIMV    192
#define DIN     384                 // 2*DIM
#define DSTATE  16
#define DTRANK  12
#define NPROJP  64                  // padded proj row stride (real cols: 44)
#define CH      8                   // scan chunks
#define CHL     (SEQL/CH)           // 72 tokens per chunk

// ---------------- scratch (device globals; no allocation) ----------------
__device__ float  g_tok [(size_t)MTOK * DIMV];            // fp32 (LN in place)
__device__ __half g_xi  [2][(size_t)MTOK * DIN];          // raw x (pre-conv)
__device__ __half g_zs  [2][(size_t)MTOK * DIN];          // silu(z)
__device__ __half g_xc  [2][(size_t)MTOK * DIN];          // silu(conv(x))
__device__ float  g_proj[2][(size_t)MTOK * NPROJP];       // [dt_raw|B|C|pad]
#define NPART (2*BATCH*CH*DIN)
__device__ float4 g_hout[(size_t)NPART*4];
__device__ float4 g_pf  [(size_t)NPART*4];
__device__ float4 g_w   [(size_t)NPART*4];
__device__ float  g_pacc[NPART];
__device__ float  g_ysum[2][BATCH * DIN];

// ---------------- packed f32x2 helpers (Blackwell) --------------------------
typedef unsigned long long ull;
__device__ __forceinline__ ull pk2(float lo, float hi) {
    ull r; asm("mov.b64 %0, {%1,%2};" : "=l"(r) : "f"(lo), "f"(hi)); return r;
}
__device__ __forceinline__ float2 upk2(ull v) {
    float2 f; asm("mov.b64 {%0,%1}, %2;" : "=f"(f.x), "=f"(f.y) : "l"(v)); return f;
}
__device__ __forceinline__ ull fma2_(ull a, ull b, ull c) {
    ull d; asm("fma.rn.f32x2 %0, %1, %2, %3;" : "=l"(d) : "l"(a), "l"(b), "l"(c)); return d;
}
__device__ __forceinline__ ull mul2_(ull a, ull b) {
    ull d; asm("mul.rn.f32x2 %0, %1, %2;" : "=l"(d) : "l"(a), "l"(b)); return d;
}

// ---------------- fp16 WMMA GEMM -------------------------------------------
#define MT 128
#define NT 64
#define KT 32
#define SBK 40
#define ASZ (MT*SBK)
#define BSZ (NT*SBK)
#define GEMM_SMEM 32768

#define CVTSTOREH(dst, off, v) do {                                           \
    __half2 h0_ = __floats2half2_rn((v).x, (v).y);                            \
    __half2 h1_ = __floats2half2_rn((v).z, (v).w);                            \
    *(__half2*)&(dst)[(off)]     = h0_;                                       \
    *(__half2*)&(dst)[(off) + 2] = h1_;                                       \
} while (0)

template<bool IMC, bool AHALF, bool ZSPLIT>
__global__ __launch_bounds__(256) void gemm_fp16_kernel(
    const void* __restrict__ A0v, const void* __restrict__ A1v,
    const float* __restrict__ W0, const float* __restrict__ W1,
    void* __restrict__ Cx0, void* __restrict__ Cx1,
    void* __restrict__ Cz0, void* __restrict__ Cz1,
    int K, int Nw, int Nout)
{
    extern __shared__ __half sm[];
    __half* As = sm;
    __half* Bs = sm + 2*ASZ;

    const void* Av = blockIdx.z ? A1v : A0v;
    const float* W = blockIdx.z ? W1 : W0;
    void* Cx = blockIdx.z ? Cx1 : Cx0;
    void* Cz = blockIdx.z ? Cz1 : Cz0;

    const int tid  = threadIdx.x;
    const int warp = tid >> 5;
    const int lane = tid & 31;
    const int wm   = warp >> 1;
    const int wn   = warp & 1;
    const int m0 = blockIdx.y * MT;
    const int n0 = blockIdx.x * NT;
    const int ar = tid >> 3, akc = (tid & 7) * 4;

    int rb[4];
    if (IMC) {
        #pragma unroll
        for (int i = 0; i < 4; i++) {
            int tok = m0 + ar + i*32;
            int b = tok / SEQL, rl = tok - b*SEQL;
            int hp = rl / 24, wp = rl - hp*24;
            rb[i] = b*442368 + hp*6144 + wp*16;
        }
    }

    wmma::fragment<wmma::accumulator,16,16,16,float> acc[2][2];
    #pragma unroll
    for (int i = 0; i < 2; i++)
        #pragma unroll
        for (int j = 0; j < 2; j++)
            wmma::fill_fragment(acc[i][j], 0.0f);

    float4 pa[4];
    uint2  pah[4];
    float4 pb[2];

    #define LOADT(k0)  do {                                                   \
        if (IMC) {                                                            \
            const float* Af = (const float*)Av;                               \
            int k_ = (k0) + akc;                                              \
            int c_ = k_ >> 8, pq_ = k_ & 255;                                 \
            int koff_ = c_*147456 + (pq_ >> 4)*384 + (pq_ & 15);              \
            _Pragma("unroll")                                                 \
            for (int i = 0; i < 4; i++)                                       \
                pa[i] = *(const float4*)&Af[rb[i] + koff_];                   \
        } else if (AHALF) {                                                   \
            const __half* Ah = (const __half*)Av;                             \
            _Pragma("unroll")                                                 \
            for (int i = 0; i < 4; i++)                                       \
                pah[i] = *(const uint2*)&Ah[(size_t)(m0 + ar + i*32)*K + (k0) + akc]; \
        } else {                                                              \
            const float* Af = (const float*)Av;                               \
            _Pragma("unroll")                                                 \
            for (int i = 0; i < 4; i++)                                       \
                pa[i] = *(const float4*)&Af[(size_t)(m0 + ar + i*32)*K + (k0) + akc]; \
        }                                                                     \
        _Pragma("unroll")                                                     \
        for (int i = 0; i < 2; i++) {                                         \
            int r_ = ar + i*32;                                               \
            pb[i] = (n0 + r_ < Nw)                                            \
                ? *(const float4*)&W[(size_t)(n0 + r_)*K + (k0) + akc]        \
                : make_float4(0.f,0.f,0.f,0.f);                               \
        }                                                                     \
    } while (0)

    #define STORET(buf)  do {                                                 \
        _Pragma("unroll")                                                     \
        for (int i = 0; i < 4; i++) {                                         \
            int off_ = (buf)*ASZ + (ar + i*32)*SBK + akc;                     \
            if (AHALF) *(uint2*)&As[off_] = pah[i];                           \
            else       CVTSTOREH(As, off_, pa[i]);                            \
        }                                                                     \
        _Pragma("unroll")                                                     \
        for (int i = 0; i < 2; i++)                                           \
            CVTSTOREH(Bs, (buf)*BSZ + (ar + i*32)*SBK + akc, pb[i]);          \
    } while (0)

    LOADT(0);
    STORET(0);
    __syncthreads();

    int buf = 0;
    for (int k0 = 0; k0 < K; k0 += KT) {
        const bool more = (k0 + KT) < K;
        if (more) LOADT(k0 + KT);
        #pragma unroll
        for (int kk = 0; kk < KT; kk += 16) {
            wmma::fragment<wmma::matrix_b,16,16,16,__half,wmma::col_major> bf[2];
            #pragma unroll
            for (int j = 0; j < 2; j++)
                wmma::load_matrix_sync(bf[j], &Bs[buf*BSZ + (wn*32 + j*16)*SBK + kk], SBK);
            #pragma unroll
            for (int i = 0; i < 2; i++) {
                wmma::fragment<wmma::matrix_a,16,16,16,__half,wmma::row_major> af;
                wmma::load_matrix_sync(af, &As[buf*ASZ + (wm*32 + i*16)*SBK + kk], SBK);
                #pragma unroll
                for (int j = 0; j < 2; j++)
                    wmma::mma_sync(acc[i][j], af, bf[j], acc[i][j]);
            }
        }
        if (more) STORET(buf ^ 1);
        __syncthreads();
        buf ^= 1;
    }
    #undef LOADT
    #undef STORET

    if (ZSPLIT) {
        __syncthreads();
        float* stage = reinterpret_cast<float*>(sm) + warp * 1024;
        #pragma unroll
        for (int i = 0; i < 2; i++)
            #pragma unroll
            for (int j = 0; j < 2; j++)
                wmma::store_matrix_sync(&stage[i*16*32 + j*16], acc[i][j], 32,
                                        wmma::mem_row_major);
        __syncwarp();
        int nbase = n0 + wn*32;
        bool isz = nbase >= DIN;
        __half* Cd = reinterpret_cast<__half*>(isz ? Cz : Cx);
        int nc0 = (isz ? nbase - DIN : nbase) + (lane & 3) * 8;
        #pragma unroll
        for (int r4 = 0; r4 < 4; r4++) {
            int row = r4*8 + (lane >> 2);
            const float* src = &stage[row*32 + (lane & 3)*8];
            __half2 h[4];
            #pragma unroll
            for (int c = 0; c < 4; c++) {
                float v0 = src[c*2], v1 = src[c*2 + 1];
                if (isz) {
                    v0 = v0 * __frcp_rn(1.0f + __expf(-v0));
                    v1 = v1 * __frcp_rn(1.0f + __expf(-v1));
                }
                h[c] = __floats2half2_rn(v0, v1);
            }
            *(uint4*)&Cd[(size_t)(m0 + wm*32 + row)*Nout + nc0] = *(uint4*)h;
        }
    } else {
        float* C = (float*)Cx;
        #pragma unroll
        for (int i = 0; i < 2; i++)
            #pragma unroll
            for (int j = 0; j < 2; j++)
                wmma::store_matrix_sync(
                    &C[(size_t)(m0 + wm*32 + i*16)*Nout + n0 + wn*32 + j*16],
                    acc[i][j], Nout, wmma::mem_row_major);
    }
}

// ---------------- LayerNorm over DIM=192 (patch bias folded in) -------------
__global__ void ln_kernel(float* __restrict__ tok, const float* __restrict__ pb,
                          const float* __restrict__ g, const float* __restrict__ b) {
    int row  = blockIdx.x * 8 + (threadIdx.x >> 5);
    int lane = threadIdx.x & 31;
    float* p = tok + (size_t)row * DIMV;
    float v[6]; float s = 0.f;
    #pragma unroll
    for (int i = 0; i < 6; i++) {
        int c = lane + i*32;
        v[i] = p[c] + pb[c];
        s += v[i];
    }
    #pragma unroll
    for (int o = 16; o; o >>= 1) s += __shfl_xor_sync(0xffffffffu, s, o);
    float mu = s * (1.0f/192.0f);
    float q = 0.f;
    #pragma unroll
    for (int i = 0; i < 6; i++) { float d = v[i] - mu; q = fmaf(d, d, q); }
    #pragma unroll
    for (int o = 16; o; o >>= 1) q += __shfl_xor_sync(0xffffffffu, q, o);
    float rstd = rsqrtf(q * (1.0f/192.0f) + 1e-5f);
    #pragma unroll
    for (int i = 0; i < 6; i++) {
        int c = lane + i*32;
        p[c] = (v[i] - mu) * rstd * g[c] + b[c];
    }
}

// ---------------- conv + silu (half in/out, fp32 math) ----------------------
__device__ __forceinline__ float4 h4tof4(uint2 u) {
    float2 a = __half22float2(*(__half2*)&u.x);
    float2 b = __half22float2(*(__half2*)&u.y);
    return make_float4(a.x, a.y, b.x, b.y);
}

__global__ __launch_bounds__(96) void conv_silu_kernel(
    const float* __restrict__ cwf, const float* __restrict__ cbf,
    const float* __restrict__ cwb, const float* __restrict__ cbb)
{
    const int dir = blockIdx.z;
    const int b   = blockIdx.y;
    const int l0  = blockIdx.x * 8;
    const int d   = threadIdx.x * 4;
    const float* cw = dir ? cwb : cwf;
    const float* cb = dir ? cbb : cbf;

    float4 a0 = *(const float4*)&cw[(d+0)*4];
    float4 a1 = *(const float4*)&cw[(d+1)*4];
    float4 a2 = *(const float4*)&cw[(d+2)*4];
    float4 a3 = *(const float4*)&cw[(d+3)*4];
    float4 t0 = make_float4(a0.x, a1.x, a2.x, a3.x);
    float4 t1 = make_float4(a0.y, a1.y, a2.y, a3.y);
    float4 t2 = make_float4(a0.z, a1.z, a2.z, a3.z);
    float4 t3 = make_float4(a0.w, a1.w, a2.w, a3.w);
    float4 bias = *(const float4*)&cb[d];

    const __half* xi = g_xi[dir];
    __half* xc = g_xc[dir];
    const int s  = dir ? -1 : 1;
    int l = dir ? (l0 + 7) : l0;

    #define LDX(ll) ((unsigned)(ll) < SEQL                                     \
        ? h4tof4(*(const uint2*)&xi[((size_t)(b*SEQL + (ll)))*DIN + d])        \
        : make_float4(0.f,0.f,0.f,0.f))

    float4 w0 = LDX(l - 3*s);
    float4 w1 = LDX(l - 2*s);
    float4 w2 = LDX(l - 1*s);

    #pragma unroll
    for (int i = 0; i < 8; i++, l += s) {
        float4 w3 = h4tof4(*(const uint2*)&xi[(size_t)(b*SEQL + l)*DIN + d]);
        float4 r;
        r.x = fmaf(t3.x, w3.x, fmaf(t2.x, w2.x, fmaf(t1.x, w1.x, fmaf(t0.x, w0.x, bias.x))));
        r.y = fmaf(t3.y, w3.y, fmaf(t2.y, w2.y, fmaf(t1.y, w1.y, fmaf(t0.y, w0.y, bias.y))));
        r.z = fmaf(t3.z, w3.z, fmaf(t2.z, w2.z, fmaf(t1.z, w1.z, fmaf(t0.z, w0.z, bias.z))));
        r.w = fmaf(t3.w, w3.w, fmaf(t2.w, w2.w, fmaf(t1.w, w1.w, fmaf(t0.w, w0.w, bias.w))));
        r.x = r.x * __frcp_rn(1.0f + __expf(-r.x));
        r.y = r.y * __frcp_rn(1.0f + __expf(-r.y));
        r.z = r.z * __frcp_rn(1.0f + __expf(-r.z));
        r.w = r.w * __frcp_rn(1.0f + __expf(-r.w));
        uint2 o;
        *(__half2*)&o.x = __floats2half2_rn(r.x, r.y);
        *(__half2*)&o.y = __floats2half2_rn(r.z, r.w);
        *(uint2*)&xc[(size_t)(b*SEQL + l)*DIN + d] = o;
        w0 = w1; w1 = w2; w2 = w3;
    }
    #undef LDX
}

// ---------------- scan part: one THREAD per (dir,b,chunk,d), f32x2 packed ----
__global__ __launch_bounds__(128) void scan_part_kernel(
    const float* __restrict__ Alf, const float* __restrict__ Df,
    const float* __restrict__ Alb, const float* __restrict__ Db,
    const float* __restrict__ dtwf, const float* __restrict__ dtbf,
    const float* __restrict__ dtwb, const float* __restrict__ dtbb)
{
    __shared__ __align__(16) float sproj[CHL][48];
    const int tid  = threadIdx.x;
    const int c    = blockIdx.y;
    const int zz   = blockIdx.z;
    const int dir  = zz / BATCH;
    const int b    = zz - dir*BATCH;
    const int d    = blockIdx.x * 128 + tid;
    const int step = dir ? -1 : 1;
    const int r0   = b*SEQL + (dir ? (SEQL - 1 - c*CHL) : c*CHL);

    const float* pp = g_proj[dir];
    for (int idx = tid; idx < CHL*12; idx += 128) {
        int row = idx / 12, q = idx - row*12;
        int rr = r0 + step*row;
        *(float4*)&sproj[row][q*4] = *(const float4*)&pp[(size_t)rr*NPROJP + q*4];
    }

    const float* Alog = dir ? Alb : Alf;
    float Dv = (dir ? Db : Df)[d];
    float a2[16];                                  // -exp(A_log) * log2(e)
    #pragma unroll
    for (int j = 0; j < 16; j++)
        a2[j] = -__expf(Alog[d*DSTATE + j]) * 1.4426950408889634f;
    const float* dtwp = dir ? dtwb : dtwf;
    float dtbias = (dir ? dtbb : dtbf)[d];
    ull dtw2[6];
    #pragma unroll
    for (int k = 0; k < 6; k++)
        dtw2[k] = pk2(dtwp[d*DTRANK + 2*k], dtwp[d*DTRANK + 2*k + 1]);
    const __half* xcp = g_xc[dir];
    const __half* zp  = g_zs[dir];

    ull h2[8], p2[8], w2[8];
    const ull ONE2  = pk2(1.f, 1.f);
    const ull ZERO2 = pk2(0.f, 0.f);
    #pragma unroll
    for (int q = 0; q < 8; q++) { h2[q] = ZERO2; p2[q] = ONE2; w2[q] = ZERO2; }
    float acc = 0.f;
    __syncthreads();

    int r = r0;
    for (int t = 0; t < CHL; t++, r += step) {
        size_t rd = (size_t)r * DIN + d;
        float xcv = __half2float(xcp[rd]);
        float zsv = __half2float(zp[rd]);
        const float* row = sproj[t];
        // dt = softplus(dot(row[0:12], dtw) + bias)   (packed dot)
        ull dp2 = ZERO2;
        #pragma unroll
        for (int k = 0; k < 6; k++)
            dp2 = fma2_(*(const ull*)&row[2*k], dtw2[k], dp2);
        float2 dpf = upk2(dp2);
        float dp = dpf.x + dpf.y + dtbias;
        float dtv = fmaxf(dp, 0.0f) + __logf(1.0f + __expf(-fabsf(dp)));
        float dtx = dtv * xcv;
        ull dtx2 = pk2(dtx, dtx);
        ull zs2  = pk2(zsv, zsv);
        ull part2 = ZERO2;
        #pragma unroll
        for (int q = 0; q < 8; q++) {
            float e0 = exp2f(dtv * a2[2*q]);
            float e1 = exp2f(dtv * a2[2*q + 1]);
            ull e2 = pk2(e0, e1);
            ull B2 = *(const ull*)&row[DTRANK + 2*q];            // j=2q,2q+1
            ull C2 = *(const ull*)&row[DTRANK + DSTATE + 2*q];
            h2[q] = fma2_(e2, h2[q], mul2_(dtx2, B2));
            p2[q] = mul2_(p2[q], e2);
            w2[q] = fma2_(mul2_(zs2, C2), p2[q], w2[q]);
            part2 = fma2_(h2[q], C2, part2);
        }
        float2 pf = upk2(part2);
        acc = fmaf(fmaf(xcv, Dv, pf.x + pf.y), zsv, acc);
    }

    size_t part_i = ((size_t)(zz*CH + c)*DIN + d);
    #pragma unroll
    for (int q = 0; q < 4; q++) {
        float2 ha = upk2(h2[2*q]), hb = upk2(h2[2*q+1]);
        float2 pa = upk2(p2[2*q]), pb = upk2(p2[2*q+1]);
        float2 wa = upk2(w2[2*q]), wb = upk2(w2[2*q+1]);
        g_hout[part_i*4 + q] = make_float4(ha.x, ha.y, hb.x, hb.y);
        g_pf  [part_i*4 + q] = make_float4(pa.x, pa.y, pb.x, pb.y);
        g_w   [part_i*4 + q] = make_float4(wa.x, wa.y, wb.x, wb.y);
    }
    g_pacc[part_i] = acc;
}

// ---------------- scan combine: one thread per (dir,b,d) --------------------
__global__ __launch_bounds__(128) void scan_combine_kernel() {
    int gid = blockIdx.x * 128 + threadIdx.x;
    if (gid >= 2 * BATCH * DIN) return;
    int zz = gid / DIN;
    int d  = gid - zz * DIN;
    float hin[16];
    #pragma unroll
    for (int j = 0; j < 16; j++) hin[j] = 0.f;
    float acc = 0.f;
    #pragma unroll
    for (int c = 0; c < CH; c++) {
        size_t part_i = ((size_t)(zz*CH + c)*DIN + d);
        float dv = 0.f;
        #pragma unroll
        for (int q = 0; q < 4; q++) {
            float4 wv = g_w[part_i*4 + q];
            dv = fmaf(wv.x, hin[q*4+0], dv);
            dv = fmaf(wv.y, hin[q*4+1], dv);
            dv = fmaf(wv.z, hin[q*4+2], dv);
            dv = fmaf(wv.w, hin[q*4+3], dv);
        }
        acc += g_pacc[part_i] + dv;
        #pragma unroll
        for (int q = 0; q < 4; q++) {
            float4 ho = g_hout[part_i*4 + q];
            float4 pf = g_pf[part_i*4 + q];
            hin[q*4+0] = fmaf(pf.x, hin[q*4+0], ho.x);
            hin[q*4+1] = fmaf(pf.y, hin[q*4+1], ho.y);
            hin[q*4+2] = fmaf(pf.z, hin[q*4+2], ho.z);
            hin[q*4+3] = fmaf(pf.w, hin[q*4+3], ho.w);
        }
    }
    int dir = zz / BATCH, b = zz - dir*BATCH;
    g_ysum[dir][b*DIN + d] = acc;
}

// ---------------- head: mean -> out_proj (both dirs) -> fc ------------------
__global__ void head_kernel(const float* __restrict__ fow, const float* __restrict__ bow,
                            const float* __restrict__ fcw, const float* __restrict__ fcb,
                            float* __restrict__ out) {
    int b = blockIdx.x;
    __shared__ float ys0[DIN], ys1[DIN], o[DIMV];
    int t = threadIdx.x;
    for (int i = t; i < DIN; i += DIMV) {
        ys0[i] = g_ysum[0][b*DIN + i] * (1.0f/SEQL);
        ys1[i] = g_ysum[1][b*DIN + i] * (1.0f/SEQL);
    }
    __syncthreads();
    float acc = 0.f;
    #pragma unroll 4
    for (int di = 0; di < DIN; di++)
        acc = fmaf(ys0[di], fow[(size_t)t*DIN + di], fmaf(ys1[di], bow[(size_t)t*DIN + di], acc));
    o[t] = acc;
    __syncthreads();
    if (t < 4) {
        float s = fcb[t];
        #pragma unroll 4
        for (int d = 0; d < DIMV; d++) s = fmaf(o[d], fcw[t*DIMV + d], s);
        out[b*4 + t] = s;
    }
}

// ---------------- launch ----------------------------------------------------
extern "C" void kernel_launch(void* const* d_in, const int* in_sizes, int n_in,
                              void* d_out, int out_size) {
    (void)in_sizes; (void)n_in; (void)out_size;
    const float* x       = (const float*)d_in[0];
    const float* patch_w = (const float*)d_in[1];
    const float* patch_b = (const float*)d_in[2];
    const float* ln_g    = (const float*)d_in[3];
    const float* ln_b    = (const float*)d_in[4];
    const float* fc_w    = (const float*)d_in[5];
    const float* fc_b    = (const float*)d_in[6];
    const float* P[2][9];
    for (int dir = 0; dir < 2; dir++)
        for (int i = 0; i < 9; i++)
            P[dir][i] = (const float*)d_in[7 + dir*9 + i];

    float *tok, *proj;
    __half *xi, *zs, *xc;
    cudaGetSymbolAddress((void**)&tok,  g_tok);
    cudaGetSymbolAddress((void**)&xi,   g_xi);
    cudaGetSymbolAddress((void**)&zs,   g_zs);
    cudaGetSymbolAddress((void**)&xc,   g_xc);
    cudaGetSymbolAddress((void**)&proj, g_proj);

    cudaFuncSetAttribute(gemm_fp16_kernel<true,false,false>,
                         cudaFuncAttributeMaxDynamicSharedMemorySize, GEMM_SMEM);
    cudaFuncSetAttribute(gemm_fp16_kernel<false,false,true>,
                         cudaFuncAttributeMaxDynamicSharedMemorySize, GEMM_SMEM);
    cudaFuncSetAttribute(gemm_fp16_kernel<false,true,false>,
                         cudaFuncAttributeMaxDynamicSharedMemorySize, GEMM_SMEM);

    // 1. patch embed GEMM with implicit im2col (bias folded into LN)
    gemm_fp16_kernel<true,false,false><<<dim3(DIMV/NT, MTOK/MT, 1), 256, GEMM_SMEM>>>(
        x, x, patch_w, patch_w, tok, tok, tok, tok, 768, DIMV, DIMV);
    // 2. layernorm in place (adds patch_b first)
    ln_kernel<<<MTOK/8, 256>>>(tok, patch_b, ln_g, ln_b);
    // 3. in-projection, both dirs; x -> g_xi (half), z -> g_zs (silu, half)
    gemm_fp16_kernel<false,false,true><<<dim3((2*DIN)/NT, MTOK/MT, 2), 256, GEMM_SMEM>>>(
        tok, tok, P[0][0], P[1][0],
        xi, xi + (size_t)MTOK*DIN,
        zs, zs + (size_t)MTOK*DIN, DIMV, 2*DIN, DIN);
    // 4. conv + silu (half -> half)
    conv_silu_kernel<<<dim3(SEQL/8, BATCH, 2), 96>>>(P[0][1], P[0][2], P[1][1], P[1][2]);
    // 5. x-projection (dt_raw | B | C); A half, weights padded 44 -> 64 cols
    gemm_fp16_kernel<false,true,false><<<dim3(1, MTOK/MT, 2), 256, GEMM_SMEM>>>(
        xc, xc + (size_t)MTOK*DIN, P[0][3], P[1][3],
        proj, proj + (size_t)MTOK*NPROJP,
        proj, proj + (size_t)MTOK*NPROJP, DIN, 44, NPROJP);
    // 6. chunked selective scan (dt fused): parts then combine
    scan_part_kernel<<<dim3(DIN/128, CH, 2*BATCH), 128>>>(
        P[0][6], P[0][7], P[1][6], P[1][7],
        P[0][4], P[0][5], P[1][4], P[1][5]);
    scan_combine_kernel<<<(2*BATCH*DIN + 127)/128, 128>>>();
    // 7. head: mean-pool -> out_w (both dirs) -> fc
    head_kernel<<<BATCH, DIMV>>>(P[0][8], P[1][8], fc_w, fc_b, (float*)d_out);
}